// round 16
// baseline (speedup 1.0000x reference)
#include <cuda_runtime.h>
#include <cuda_bf16.h>
#include <math.h>

// Problem constants (fixed by the reference setup)
#define BB 4
#define CC 32
#define NCP 16          // channel pairs
#define PP 262144       // 512*512 pixels per image
#define NI 100          // n_instances
#define CHUNK 2048      // pixels per block
#define TPB 512
#define NCOPY 8         // bank-sliced histogram copies
#define NBLK 512        // 4 batches x 128 chunks
#define NDIST 8         // distance blocks: 2 per batch
#define NBLK2 (NBLK + NDIST)   // 520

// Scratch (no device allocation allowed -> __device__ globals).
// Zero at module load; pass2's ticket block re-zeros accumulators after each
// run. g_inbf is fully overwritten by pass1 every run (no cleanup needed).
__device__ float g_sums[BB*CC*NI];   // [b][c*NI+k]
__device__ int   g_counts[BB*NI];
__device__ uint4 g_inbf[BB*NCP*PP/4]; // bf16x2 channel-pair mirror of the input
__device__ float g_var[BB];
__device__ float g_dist[BB];         // atomically accumulated every run
__device__ float g_reg[BB];          // plain-stored every run
__device__ unsigned int g_t2;

// -------- Pass 1: per-label sums (bf16x2 atomics) + bf16 input mirror --------
__global__ __launch_bounds__(TPB) void pass1_k(const float* __restrict__ in,
                                               const int* __restrict__ tgt) {
    __shared__ __align__(16) __nv_bfloat162 ssum[NCP*NI*NCOPY]; // [(cp*100+k)*8+copy]
    __shared__ int scnt[NI];

    int blk   = blockIdx.x;
    int b     = blk >> 7;           // /128
    int chunk = blk & 127;
    int p0    = chunk * CHUNK;
    int t     = threadIdx.x;
    int cpy   = t & (NCOPY-1);

    for (int i = t; i < NCP*NI*NCOPY/8; i += TPB) {
        ((uint4*)ssum)[i*2]   = make_uint4(0,0,0,0);
        ((uint4*)ssum)[i*2+1] = make_uint4(0,0,0,0);
    }
    for (int i = t; i < NI; i += TPB) scnt[i] = 0;
    __syncthreads();

    const int4* tg = (const int4*)(tgt + (size_t)b * PP + p0);
    int4 lv = tg[t];
    int lbl[4] = {lv.x, lv.y, lv.z, lv.w};
#pragma unroll
    for (int k = 0; k < 4; k++) atomicAdd(&scnt[lbl[k]], 1);

    int s0 = lbl[0]*NCOPY + cpy;
    int s1 = lbl[1]*NCOPY + cpy;
    int s2 = lbl[2]*NCOPY + cpy;
    int s3 = lbl[3]*NCOPY + cpy;

    const float* base = in + (size_t)b * CC * PP + p0;
#pragma unroll 2
    for (int cp = 0; cp < NCP; cp++) {
        const float4* pc0 = (const float4*)(base + (size_t)(2*cp)   * PP);
        const float4* pc1 = (const float4*)(base + (size_t)(2*cp+1) * PP);
        float4 v0 = pc0[t];
        float4 v1 = pc1[t];
        __nv_bfloat162 p0v = __floats2bfloat162_rn(v0.x, v1.x);
        __nv_bfloat162 p1v = __floats2bfloat162_rn(v0.y, v1.y);
        __nv_bfloat162 p2v = __floats2bfloat162_rn(v0.z, v1.z);
        __nv_bfloat162 p3v = __floats2bfloat162_rn(v0.w, v1.w);
        // mirror: 4 consecutive pixels' (2cp,2cp+1) bf16x2 -> one STG.128
        g_inbf[(((size_t)b*NCP + cp)*PP + p0 >> 2) + t] =
            make_uint4(*(unsigned int*)&p0v, *(unsigned int*)&p1v,
                       *(unsigned int*)&p2v, *(unsigned int*)&p3v);
        int cb = cp*NI*NCOPY;
        atomicAdd(&ssum[cb + s0], p0v);
        atomicAdd(&ssum[cb + s1], p1v);
        atomicAdd(&ssum[cb + s2], p2v);
        atomicAdd(&ssum[cb + s3], p3v);
    }
    __syncthreads();

    // flush: vectorized read of the 8 copies (32B = 2 x uint4), bf16 -> fp32
    float* gs = g_sums + (size_t)b * CC * NI;
    for (int i = t; i < NCP*NI; i += TPB) {
        int cp = i / NI;
        int k  = i - cp * NI;
        uint4 a = ((const uint4*)ssum)[i*2];
        uint4 c = ((const uint4*)ssum)[i*2+1];
        float sx = 0.f, sy = 0.f;
        unsigned int w[8] = {a.x, a.y, a.z, a.w, c.x, c.y, c.z, c.w};
#pragma unroll
        for (int j = 0; j < 8; j++) {
            __nv_bfloat162 v = *(__nv_bfloat162*)&w[j];
            sx += __bfloat162float(v.x);
            sy += __bfloat162float(v.y);
        }
        atomicAdd(&gs[(2*cp)   * NI + k], sx);
        atomicAdd(&gs[(2*cp+1) * NI + k], sy);
    }
    int* gc = g_counts + b * NI;
    for (int i = t; i < NI; i += TPB) atomicAdd(&gc[i], scnt[i]);
}

// -------- Pass 2: 512 variance blocks (bf16 mirror input) + 8 dist + final ----
__global__ __launch_bounds__(TPB) void pass2_k(const int* __restrict__ tgt,
                                               float* __restrict__ out) {
    __shared__ float sh[NI*33 + NI + 32];
    __shared__ bool s_last;
    int blk = blockIdx.x;
    int t   = threadIdx.x;

    if (blk < NBLK) {
        // ---- variance term: bf16x2 means + bf16x2 mirrored input ----
        __nv_bfloat162* smean2 = (__nv_bfloat162*)sh;      // [cp*100+k], 1600
        float* sinv = sh + NCP*NI;                         // [k]
        float* red  = sh + NCP*NI + NI;

        int b  = blk >> 7;
        int p0 = (blk & 127) * CHUNK;

        const float* gs = g_sums + (size_t)b * CC * NI;
        const int*   gc = g_counts + b * NI;
        for (int i = t; i < NI; i += TPB) {
            int cnt = gc[i];
            sinv[i] = (cnt > 0) ? __frcp_rn((float)cnt) : 0.f;
        }
        __syncthreads();
        for (int i = t; i < NCP*NI; i += TPB) {
            int cp = i / NI;
            int k  = i - cp * NI;
            float iv = sinv[k];
            float mx = gs[(2*cp)   * NI + k] * iv;
            float my = gs[(2*cp+1) * NI + k] * iv;
            smean2[i] = __floats2bfloat162_rn(mx, my);
        }
        __syncthreads();

        const int4* tg = (const int4*)(tgt + (size_t)b * PP + p0);
        int4 lv = tg[t];
        int lbl[4] = {lv.x, lv.y, lv.z, lv.w};

        float acc[4] = {0.f, 0.f, 0.f, 0.f};
#pragma unroll 4
        for (int cp = 0; cp < NCP; cp++) {
            uint4 w = g_inbf[(((size_t)b*NCP + cp)*PP + p0 >> 2) + t];
            int cb = cp*NI;
            __nv_bfloat162 f0 = *(__nv_bfloat162*)&w.x;
            __nv_bfloat162 f1 = *(__nv_bfloat162*)&w.y;
            __nv_bfloat162 f2 = *(__nv_bfloat162*)&w.z;
            __nv_bfloat162 f3 = *(__nv_bfloat162*)&w.w;
            __nv_bfloat162 m0 = smean2[cb + lbl[0]];
            __nv_bfloat162 m1 = smean2[cb + lbl[1]];
            __nv_bfloat162 m2 = smean2[cb + lbl[2]];
            __nv_bfloat162 m3 = smean2[cb + lbl[3]];
            float d0a = __bfloat162float(f0.x) - __bfloat162float(m0.x);
            float d0b = __bfloat162float(f0.y) - __bfloat162float(m0.y);
            float d1a = __bfloat162float(f1.x) - __bfloat162float(m1.x);
            float d1b = __bfloat162float(f1.y) - __bfloat162float(m1.y);
            float d2a = __bfloat162float(f2.x) - __bfloat162float(m2.x);
            float d2b = __bfloat162float(f2.y) - __bfloat162float(m2.y);
            float d3a = __bfloat162float(f3.x) - __bfloat162float(m3.x);
            float d3b = __bfloat162float(f3.y) - __bfloat162float(m3.y);
            acc[0] = fmaf(d0a, d0a, acc[0]); acc[0] = fmaf(d0b, d0b, acc[0]);
            acc[1] = fmaf(d1a, d1a, acc[1]); acc[1] = fmaf(d1b, d1b, acc[1]);
            acc[2] = fmaf(d2a, d2a, acc[2]); acc[2] = fmaf(d2b, d2b, acc[2]);
            acc[3] = fmaf(d3a, d3a, acc[3]); acc[3] = fmaf(d3b, d3b, acc[3]);
        }

        float local = 0.f;
#pragma unroll
        for (int k = 0; k < 4; k++) {
            float n = sqrtf(acc[k]);
            float h = fmaxf(n - 0.75f, 0.f);   // DELTA_VAR
            local += h * h * sinv[lbl[k]];
        }
#pragma unroll
        for (int o = 16; o > 0; o >>= 1) local += __shfl_down_sync(0xffffffffu, local, o);
        if ((t & 31) == 0) red[t >> 5] = local;
        __syncthreads();
        if (t < 32) {
            float v = (t < TPB/32) ? red[t] : 0.f;
#pragma unroll
            for (int o = 16; o > 0; o >>= 1) v += __shfl_down_sync(0xffffffffu, v, o);
            if (t == 0) atomicAdd(&g_var[b], v);
        }
    } else {
        // ---- distance + reg terms: 2 blocks per batch (fp32 means) ----
        float* sm   = sh;                  // [k*33+c] padded
        float* sinv = sh + NI*33;
        int d    = blk - NBLK;
        int b    = d >> 1;
        int half = d & 1;

        const float* gs = g_sums + (size_t)b * CC * NI;
        const int*   gc = g_counts + b * NI;
        if (t < NI) {
            int cnt = gc[t];
            sinv[t] = (cnt > 0) ? __frcp_rn((float)cnt) : 0.f;
        }
        __syncthreads();
        for (int i = t; i < CC*NI; i += TPB) {
            int c = i / NI;
            int k = i - c * NI;
            sm[k*33 + c] = gs[i] * sinv[k];
        }
        if (t == 0) sh[NI*33 + NI] = 0.f;   // reg accumulator
        __syncthreads();

        // reg term (first half-block only)
        if (half == 0 && t < NI) {
            float s = 0.f;
#pragma unroll
            for (int c = 0; c < CC; c++) { float m = sm[t*33 + c]; s = fmaf(m, m, s); }
            atomicAdd(&sh[NI*33 + NI], sqrtf(s));
        }

        // distance term: this block handles pair-indices [half*5000, half*5000+5000)
        float local = 0.f;
        for (int idx = half*5000 + t; idx < half*5000 + 5000; idx += TPB) {
            int i = idx / NI;
            int j = idx - i * NI;
            if (i != j) {
                float d2 = 0.f;
#pragma unroll
                for (int c = 0; c < CC; c++) {
                    float dd = sm[i*33 + c] - sm[j*33 + c];
                    d2 = fmaf(dd, dd, d2);
                }
                float dist = (d2 > 0.f) ? sqrtf(d2) : 1.f;   // jnp.where(d2>0, d2, 1)
                float h = fmaxf(4.f - dist, 0.f);            // 2*DELTA_DIST
                local += h * h;
            }
        }
        float* red = sh + NI*33 + NI + 1;
#pragma unroll
        for (int o = 16; o > 0; o >>= 1) local += __shfl_down_sync(0xffffffffu, local, o);
        if ((t & 31) == 0) red[t >> 5] = local;
        __syncthreads();
        if (t < 32) {
            float v = (t < TPB/32) ? red[t] : 0.f;
#pragma unroll
            for (int o = 16; o > 0; o >>= 1) v += __shfl_down_sync(0xffffffffu, v, o);
            if (t == 0) {
                atomicAdd(&g_dist[b], v);
                if (half == 0) g_reg[b] = sh[NI*33 + NI];
            }
        }
    }

    // ---- ticket: last block -> final combine + replay cleanup ----
    __syncthreads();
    if (t == 0) {
        __threadfence();
        unsigned r = atomicAdd(&g_t2, 1u);
        s_last = (r == NBLK2 - 1);
    }
    __syncthreads();
    if (s_last) {
        if (t == 0) {
            float s = 0.f;
#pragma unroll
            for (int bb = 0; bb < BB; bb++) {
                float var_term  = g_var[bb]  * (1.f / (float)NI);
                float dist_term = g_dist[bb] * (1.f / (float)(NI * (NI - 1)));
                float reg_term  = g_reg[bb]  * (1.f / (float)NI);
                s += var_term + dist_term + 0.001f * reg_term;
            }
            out[0] = s * (1.f / (float)BB);
        }
        // cleanup for next graph replay (disjoint from t0's work above)
        for (int i = t; i < BB*CC*NI; i += TPB) g_sums[i] = 0.f;
        for (int i = t; i < BB*NI;    i += TPB) g_counts[i] = 0;
        __syncthreads();
        if (t < BB) { g_var[t] = 0.f; g_dist[t] = 0.f; }
        if (t == 0) g_t2 = 0u;
    }
}

extern "C" void kernel_launch(void* const* d_in, const int* in_sizes, int n_in,
                              void* d_out, int out_size) {
    const float* in  = (const float*)d_in[0];
    const int*   tgt = (const int*)d_in[1];
    float*       out = (float*)d_out;
    (void)in_sizes; (void)n_in; (void)out_size;

    pass1_k<<<NBLK, TPB>>>(in, tgt);
    pass2_k<<<NBLK2, TPB>>>(tgt, out);
}

// round 17
// speedup vs baseline: 1.2649x; 1.2649x over previous
#include <cuda_runtime.h>
#include <cuda_bf16.h>
#include <math.h>

// Problem constants (fixed by the reference setup)
#define BB 4
#define CC 32
#define NCP 16          // channel pairs total
#define HCP 8           // channel pairs per pass1 block (half)
#define PP 262144       // 512*512 pixels per image
#define NI 100          // n_instances
#define CHUNK 2048      // pixels per block
#define TPB 512
#define NCOPY 8         // bank-sliced histogram copies
#define NBLK1 1024      // pass1: 4 batches x 128 chunks x 2 channel-halves
#define NBLK 512        // pass2 variance blocks
#define NDIST 8         // distance blocks: 2 per batch
#define NBLK2 (NBLK + NDIST)   // 520

// Scratch (no device allocation allowed -> __device__ globals).
// Zero at module load; pass2's ticket block re-zeros accumulators after each
// run so every graph replay starts clean.
__device__ float g_sums[BB*CC*NI];   // [b][c*NI+k]
__device__ int   g_counts[BB*NI];
__device__ float g_var[BB];
__device__ float g_dist[BB];         // atomically accumulated every run
__device__ float g_reg[BB];          // plain-stored every run
__device__ unsigned int g_t2;

// -------- Pass 1: per-label sums (bf16x2 atomics, 8-way bank-sliced) --------
// Each block handles 8 channel-pairs of one 2048-pixel chunk -> 25.6KB smem
// -> full 2048 threads/SM residency (4 blocks x 512).
__global__ __launch_bounds__(TPB) void pass1_k(const float* __restrict__ in,
                                               const int* __restrict__ tgt) {
    __shared__ __align__(16) __nv_bfloat162 ssum[HCP*NI*NCOPY]; // [(cpl*100+k)*8+copy]
    __shared__ int scnt[NI];

    int blk    = blockIdx.x;
    int b      = blk >> 8;          // /256
    int rest   = blk & 255;
    int chunk  = rest >> 1;
    int chalf  = rest & 1;          // which 8 channel-pairs
    int p0     = chunk * CHUNK;
    int t      = threadIdx.x;
    int cpy    = t & (NCOPY-1);

    for (int i = t; i < HCP*NI*NCOPY/8; i += TPB) {
        ((uint4*)ssum)[i*2]   = make_uint4(0,0,0,0);
        ((uint4*)ssum)[i*2+1] = make_uint4(0,0,0,0);
    }
    if (chalf == 0) for (int i = t; i < NI; i += TPB) scnt[i] = 0;
    __syncthreads();

    const int4* tg = (const int4*)(tgt + (size_t)b * PP + p0);
    int4 lv = tg[t];
    int lbl[4] = {lv.x, lv.y, lv.z, lv.w};
    if (chalf == 0) {
#pragma unroll
        for (int k = 0; k < 4; k++) atomicAdd(&scnt[lbl[k]], 1);
    }

    int s0 = lbl[0]*NCOPY + cpy;
    int s1 = lbl[1]*NCOPY + cpy;
    int s2 = lbl[2]*NCOPY + cpy;
    int s3 = lbl[3]*NCOPY + cpy;

    const float* base = in + (size_t)b * CC * PP + p0 + (size_t)(2*HCP*chalf) * PP;
#pragma unroll 2
    for (int cpl = 0; cpl < HCP; cpl++) {
        const float4* pc0 = (const float4*)(base + (size_t)(2*cpl)   * PP);
        const float4* pc1 = (const float4*)(base + (size_t)(2*cpl+1) * PP);
        float4 v0 = pc0[t];
        float4 v1 = pc1[t];
        __nv_bfloat162 p0v = __floats2bfloat162_rn(v0.x, v1.x);
        __nv_bfloat162 p1v = __floats2bfloat162_rn(v0.y, v1.y);
        __nv_bfloat162 p2v = __floats2bfloat162_rn(v0.z, v1.z);
        __nv_bfloat162 p3v = __floats2bfloat162_rn(v0.w, v1.w);
        int cb = cpl*NI*NCOPY;
        atomicAdd(&ssum[cb + s0], p0v);
        atomicAdd(&ssum[cb + s1], p1v);
        atomicAdd(&ssum[cb + s2], p2v);
        atomicAdd(&ssum[cb + s3], p3v);
    }
    __syncthreads();

    // flush: vectorized read of the 8 copies (32B = 2 x uint4), bf16 -> fp32
    float* gs = g_sums + (size_t)b * CC * NI;
    for (int i = t; i < HCP*NI; i += TPB) {
        int cpl = i / NI;
        int k   = i - cpl * NI;
        int cp  = chalf*HCP + cpl;
        uint4 a = ((const uint4*)ssum)[i*2];
        uint4 c = ((const uint4*)ssum)[i*2+1];
        float sx = 0.f, sy = 0.f;
        unsigned int w[8] = {a.x, a.y, a.z, a.w, c.x, c.y, c.z, c.w};
#pragma unroll
        for (int j = 0; j < 8; j++) {
            __nv_bfloat162 v = *(__nv_bfloat162*)&w[j];
            sx += __bfloat162float(v.x);
            sy += __bfloat162float(v.y);
        }
        atomicAdd(&gs[(2*cp)   * NI + k], sx);
        atomicAdd(&gs[(2*cp+1) * NI + k], sy);
    }
    if (chalf == 0) {
        int* gc = g_counts + b * NI;
        for (int i = t; i < NI; i += TPB) atomicAdd(&gc[i], scnt[i]);
    }
}

// -------- Pass 2: 512 variance blocks (bf16x2 packed means) + 8 dist + final --
__global__ __launch_bounds__(TPB) void pass2_k(const float* __restrict__ in,
                                               const int* __restrict__ tgt,
                                               float* __restrict__ out) {
    __shared__ float sh[NI*33 + NI + 32];
    __shared__ bool s_last;
    int blk = blockIdx.x;
    int t   = threadIdx.x;

    if (blk < NBLK) {
        // ---- variance term: means packed bf16x2 by channel pair ----
        __nv_bfloat162* smean2 = (__nv_bfloat162*)sh;      // [cp*100+k], 1600
        float* sinv = sh + NCP*NI;                         // [k]
        float* red  = sh + NCP*NI + NI;

        int b  = blk >> 7;
        int p0 = (blk & 127) * CHUNK;

        const float* gs = g_sums + (size_t)b * CC * NI;
        const int*   gc = g_counts + b * NI;
        for (int i = t; i < NI; i += TPB) {
            int cnt = gc[i];
            sinv[i] = (cnt > 0) ? __frcp_rn((float)cnt) : 0.f;
        }
        __syncthreads();
        for (int i = t; i < NCP*NI; i += TPB) {
            int cp = i / NI;
            int k  = i - cp * NI;
            float iv = sinv[k];
            float mx = gs[(2*cp)   * NI + k] * iv;
            float my = gs[(2*cp+1) * NI + k] * iv;
            smean2[i] = __floats2bfloat162_rn(mx, my);
        }
        __syncthreads();

        const int4* tg = (const int4*)(tgt + (size_t)b * PP + p0);
        int4 lv = tg[t];
        int lbl[4] = {lv.x, lv.y, lv.z, lv.w};

        float acc[4] = {0.f, 0.f, 0.f, 0.f};
        const float* base = in + (size_t)b * CC * PP + p0;
#pragma unroll 4
        for (int cp = 0; cp < NCP; cp++) {
            const float4* pc0 = (const float4*)(base + (size_t)(2*cp)   * PP);
            const float4* pc1 = (const float4*)(base + (size_t)(2*cp+1) * PP);
            float4 v0 = pc0[t];
            float4 v1 = pc1[t];
            int cb = cp*NI;
            __nv_bfloat162 m0 = smean2[cb + lbl[0]];
            __nv_bfloat162 m1 = smean2[cb + lbl[1]];
            __nv_bfloat162 m2 = smean2[cb + lbl[2]];
            __nv_bfloat162 m3 = smean2[cb + lbl[3]];
            float d0a = v0.x - __bfloat162float(m0.x);
            float d0b = v1.x - __bfloat162float(m0.y);
            float d1a = v0.y - __bfloat162float(m1.x);
            float d1b = v1.y - __bfloat162float(m1.y);
            float d2a = v0.z - __bfloat162float(m2.x);
            float d2b = v1.z - __bfloat162float(m2.y);
            float d3a = v0.w - __bfloat162float(m3.x);
            float d3b = v1.w - __bfloat162float(m3.y);
            acc[0] = fmaf(d0a, d0a, acc[0]); acc[0] = fmaf(d0b, d0b, acc[0]);
            acc[1] = fmaf(d1a, d1a, acc[1]); acc[1] = fmaf(d1b, d1b, acc[1]);
            acc[2] = fmaf(d2a, d2a, acc[2]); acc[2] = fmaf(d2b, d2b, acc[2]);
            acc[3] = fmaf(d3a, d3a, acc[3]); acc[3] = fmaf(d3b, d3b, acc[3]);
        }

        float local = 0.f;
#pragma unroll
        for (int k = 0; k < 4; k++) {
            float n = sqrtf(acc[k]);
            float h = fmaxf(n - 0.75f, 0.f);   // DELTA_VAR
            local += h * h * sinv[lbl[k]];
        }
#pragma unroll
        for (int o = 16; o > 0; o >>= 1) local += __shfl_down_sync(0xffffffffu, local, o);
        if ((t & 31) == 0) red[t >> 5] = local;
        __syncthreads();
        if (t < 32) {
            float v = (t < TPB/32) ? red[t] : 0.f;
#pragma unroll
            for (int o = 16; o > 0; o >>= 1) v += __shfl_down_sync(0xffffffffu, v, o);
            if (t == 0) atomicAdd(&g_var[b], v);
        }
    } else {
        // ---- distance + reg terms: 2 blocks per batch (fp32 means) ----
        float* sm   = sh;                  // [k*33+c] padded
        float* sinv = sh + NI*33;
        int d    = blk - NBLK;
        int b    = d >> 1;
        int half = d & 1;

        const float* gs = g_sums + (size_t)b * CC * NI;
        const int*   gc = g_counts + b * NI;
        if (t < NI) {
            int cnt = gc[t];
            sinv[t] = (cnt > 0) ? __frcp_rn((float)cnt) : 0.f;
        }
        __syncthreads();
        for (int i = t; i < CC*NI; i += TPB) {
            int c = i / NI;
            int k = i - c * NI;
            sm[k*33 + c] = gs[i] * sinv[k];
        }
        if (t == 0) sh[NI*33 + NI] = 0.f;   // reg accumulator
        __syncthreads();

        // reg term (first half-block only)
        if (half == 0 && t < NI) {
            float s = 0.f;
#pragma unroll
            for (int c = 0; c < CC; c++) { float m = sm[t*33 + c]; s = fmaf(m, m, s); }
            atomicAdd(&sh[NI*33 + NI], sqrtf(s));
        }

        // distance term: this block handles pair-indices [half*5000, half*5000+5000)
        float local = 0.f;
        for (int idx = half*5000 + t; idx < half*5000 + 5000; idx += TPB) {
            int i = idx / NI;
            int j = idx - i * NI;
            if (i != j) {
                float d2 = 0.f;
#pragma unroll
                for (int c = 0; c < CC; c++) {
                    float dd = sm[i*33 + c] - sm[j*33 + c];
                    d2 = fmaf(dd, dd, d2);
                }
                float dist = (d2 > 0.f) ? sqrtf(d2) : 1.f;   // jnp.where(d2>0, d2, 1)
                float h = fmaxf(4.f - dist, 0.f);            // 2*DELTA_DIST
                local += h * h;
            }
        }
        float* red = sh + NI*33 + NI + 1;
#pragma unroll
        for (int o = 16; o > 0; o >>= 1) local += __shfl_down_sync(0xffffffffu, local, o);
        if ((t & 31) == 0) red[t >> 5] = local;
        __syncthreads();
        if (t < 32) {
            float v = (t < TPB/32) ? red[t] : 0.f;
#pragma unroll
            for (int o = 16; o > 0; o >>= 1) v += __shfl_down_sync(0xffffffffu, v, o);
            if (t == 0) {
                atomicAdd(&g_dist[b], v);
                if (half == 0) g_reg[b] = sh[NI*33 + NI];
            }
        }
    }

    // ---- ticket: last block -> final combine + replay cleanup ----
    __syncthreads();
    if (t == 0) {
        __threadfence();
        unsigned r = atomicAdd(&g_t2, 1u);
        s_last = (r == NBLK2 - 1);
    }
    __syncthreads();
    if (s_last) {
        if (t == 0) {
            float s = 0.f;
#pragma unroll
            for (int bb = 0; bb < BB; bb++) {
                float var_term  = g_var[bb]  * (1.f / (float)NI);
                float dist_term = g_dist[bb] * (1.f / (float)(NI * (NI - 1)));
                float reg_term  = g_reg[bb]  * (1.f / (float)NI);
                s += var_term + dist_term + 0.001f * reg_term;
            }
            out[0] = s * (1.f / (float)BB);
        }
        // cleanup for next graph replay (disjoint from t0's work above)
        for (int i = t; i < BB*CC*NI; i += TPB) g_sums[i] = 0.f;
        for (int i = t; i < BB*NI;    i += TPB) g_counts[i] = 0;
        __syncthreads();
        if (t < BB) { g_var[t] = 0.f; g_dist[t] = 0.f; }
        if (t == 0) g_t2 = 0u;
    }
}

extern "C" void kernel_launch(void* const* d_in, const int* in_sizes, int n_in,
                              void* d_out, int out_size) {
    const float* in  = (const float*)d_in[0];
    const int*   tgt = (const int*)d_in[1];
    float*       out = (float*)d_out;
    (void)in_sizes; (void)n_in; (void)out_size;

    pass1_k<<<NBLK1, TPB>>>(in, tgt);
    pass2_k<<<NBLK2, TPB>>>(in, tgt, out);
}